// round 12
// baseline (speedup 1.0000x reference)
#include <cuda_runtime.h>
#include <math_constants.h>

#define BATCH 32
#define HDIM 1024
#define NHEADS 16
#define HD 64
#define BS 16
#define MAX_KV 2048
#define BLOCKS_PER_SEQ 128
#define SCALE 0.125f

#define QSPLIT 32         // i-chunks for projections (1024/32)
#define ICHUNK 32
#define KVSPLIT 8         // splits over KV sequence
#define CHUNK 256         // tokens per split

// scratch (allocation-free rule: device globals)
__device__ float  g_qpart[QSPLIT * BATCH * HDIM];          // 4 MB
__device__ float  g_opart[QSPLIT * BATCH * HDIM];          // 4 MB
__device__ float  g_part [KVSPLIT * BATCH * NHEADS * HD];  // 1 MB
__device__ float  g_l    [KVSPLIT * BATCH * NHEADS];       // denom per split

// ---------------------------------------------------------------------------
// qproj partial: g_qpart[ic][b][j] = sum_{i in chunk} h[b][i]*w[i][j]
// grid (16 j-tiles, QSPLIT i-chunks) = 512 CTAs, 256 thr = 64 j x 4 bgroups(x8)
// ---------------------------------------------------------------------------
__global__ void qproj_kernel(const float* __restrict__ h,
                             const float* __restrict__ w) {
    const int jt = blockIdx.x;          // 0..15
    const int ic = blockIdx.y;          // 0..QSPLIT-1
    const int tid = threadIdx.x;
    const int j  = jt * 64 + (tid & 63);
    const int bg = tid >> 6;            // 0..3 -> batches bg*8..bg*8+7

    __shared__ float hs[ICHUNK][BATCH]; // [i][b], 4 KB
    for (int idx = tid; idx < ICHUNK * BATCH; idx += 256) {
        int i = idx >> 5, b = idx & 31;
        hs[i][b] = h[b * HDIM + ic * ICHUNK + i];
    }
    __syncthreads();

    float acc0=0,acc1=0,acc2=0,acc3=0,acc4=0,acc5=0,acc6=0,acc7=0;
    const float* wp = w + (size_t)(ic * ICHUNK) * (3 * HDIM) + j;
#pragma unroll 8
    for (int i = 0; i < ICHUNK; i++) {
        float wv = wp[(size_t)i * (3 * HDIM)];
        float4 ha = *(const float4*)&hs[i][bg * 8];
        float4 hb = *(const float4*)&hs[i][bg * 8 + 4];
        acc0 = fmaf(wv, ha.x, acc0);
        acc1 = fmaf(wv, ha.y, acc1);
        acc2 = fmaf(wv, ha.z, acc2);
        acc3 = fmaf(wv, ha.w, acc3);
        acc4 = fmaf(wv, hb.x, acc4);
        acc5 = fmaf(wv, hb.y, acc5);
        acc6 = fmaf(wv, hb.z, acc6);
        acc7 = fmaf(wv, hb.w, acc7);
    }
    float* po = g_qpart + (size_t)ic * BATCH * HDIM + (size_t)(bg * 8) * HDIM + j;
    po[0*HDIM]=acc0; po[1*HDIM]=acc1; po[2*HDIM]=acc2; po[3*HDIM]=acc3;
    po[4*HDIM]=acc4; po[5*HDIM]=acc5; po[6*HDIM]=acc6; po[7*HDIM]=acc7;
}

// ---------------------------------------------------------------------------
// Flash-decode attention, split-KV. grid (NHEADS, BATCH, KVSPLIT), 256 thr.
// Prologue folds the 32 qproj partials + bias (fused qreduce).
// No online rescale: scores are O(1); exp clamped at 60 for hard safety.
// ---------------------------------------------------------------------------
__global__ void attn_kernel(const float* __restrict__ kv,
                            const int* __restrict__ btab,
                            const int* __restrict__ slen,
                            const float* __restrict__ b_attn) {
    const int n  = blockIdx.x;
    const int b  = blockIdx.y;
    const int sp = blockIdx.z;
    const int tid = threadIdx.x;
    const int L = slen[b];
    const int start = sp * CHUNK;
    const int end = min(L, start + CHUNK);
    const int pidx = (sp * BATCH + b) * NHEADS + n;

    if (start >= end) {   // empty split: neutral partial (uniform across CTA)
        if (tid < HD) g_part[pidx * HD + tid] = 0.f;
        if (tid == 0) g_l[pidx] = 0.f;
        return;
    }

    __shared__ float sq[HD];
    __shared__ int   sbt[CHUNK / BS];          // 16 block ids for this chunk
    __shared__ float smacc[16][HD];            // per half-warp V accum
    __shared__ float sml[16];                  // per half-warp denom

    if (tid < HD) {
        float s = b_attn[n * HD + tid];
        const float* qp = g_qpart + b * HDIM + n * HD + tid;
#pragma unroll
        for (int p = 0; p < QSPLIT; p++)
            s += qp[p * BATCH * HDIM];
        sq[tid] = s * SCALE;
    }
    if (tid < CHUNK / BS)
        sbt[tid] = btab[b * BLOCKS_PER_SEQ + (start >> 4) + tid];
    __syncthreads();

    const int lane = tid & 31;
    const int warp = tid >> 5;        // 0..7
    const int half = lane >> 4;       // 0/1
    const int hl   = lane & 15;       // lane within half-warp
    const int hw   = warp * 2 + half; // half-warp id 0..15
    const float4 q4 = ((const float4*)sq)[hl];

    const float* kbase = kv;
    const float* vbase = kv + (size_t)4096 * BS * NHEADS * HD;

    float l = 0.f;
    float4 acc = make_float4(0.f, 0.f, 0.f, 0.f);

    // uniform iteration count across the whole CTA
    const int NIT = (end - start + 15) >> 4;
#pragma unroll 4
    for (int it = 0; it < NIT; it++) {
        const int t = start + hw + it * 16;
        const bool valid = (t < end);
        // redirect invalid lanes to a safe address within the chunk
        const int ts = valid ? t : start;
        const int blk = sbt[(ts - start) >> 4];
        const size_t off = (((size_t)blk * BS + (ts & 15)) * NHEADS + n) * HD + hl * 4;
        const float4 k4 = __ldcs((const float4*)(kbase + off));
        const float4 v4 = __ldcs((const float4*)(vbase + off));
        float p = fmaf(k4.x, q4.x, fmaf(k4.y, q4.y, fmaf(k4.z, q4.z, k4.w * q4.w)));
#pragma unroll
        for (int o = 8; o > 0; o >>= 1)
            p += __shfl_xor_sync(0xffffffffu, p, o);
        if (!valid) p = -CUDART_INF_F;          // exp(-inf) = 0: neutral
        const float e = __expf(fminf(p, 60.f));
        acc.x = fmaf(e, v4.x, acc.x);
        acc.y = fmaf(e, v4.y, acc.y);
        acc.z = fmaf(e, v4.z, acc.z);
        acc.w = fmaf(e, v4.w, acc.w);
        l += e;
    }

    ((float4*)smacc[hw])[hl] = acc;
    if (hl == 0) sml[hw] = l;
    __syncthreads();

    if (tid < HD) {
        float num = 0.f, den = 0.f;
#pragma unroll
        for (int i = 0; i < 16; i++) {
            num += smacc[i][tid];
            den += sml[i];
        }
        g_part[pidx * HD + tid] = num;
        if (tid == 0) g_l[pidx] = den;
    }
}

// ---------------------------------------------------------------------------
// oproj partial with fused attn_reduce: hs is computed from g_part/g_l.
// g_opart[ic][b][j] = sum_{i in chunk} attn[b][i]*w[i][j]
// ---------------------------------------------------------------------------
__global__ void oproj_kernel(const float* __restrict__ w) {
    const int jt = blockIdx.x;          // 0..15
    const int ic = blockIdx.y;          // 0..QSPLIT-1
    const int tid = threadIdx.x;
    const int j  = jt * 64 + (tid & 63);
    const int bg = tid >> 6;            // 0..3 -> batches bg*8..bg*8+7

    __shared__ float hs[ICHUNK][BATCH]; // [i][b], 4 KB
    for (int idx = tid; idx < ICHUNK * BATCH; idx += 256) {
        const int i = idx >> 5, b = idx & 31;
        const int ig = ic * ICHUNK + i;        // global hidden index
        const int n = ig >> 6;                 // head
        const int d = ig & 63;                 // dim within head
        float num = 0.f, den = 0.f;
#pragma unroll
        for (int s = 0; s < KVSPLIT; s++) {
            const int pidx = (s * BATCH + b) * NHEADS + n;
            num += g_part[pidx * HD + d];
            den += g_l[pidx];
        }
        hs[i][b] = num / den;
    }
    __syncthreads();

    float acc0=0,acc1=0,acc2=0,acc3=0,acc4=0,acc5=0,acc6=0,acc7=0;
    const float* wp = w + (size_t)(ic * ICHUNK) * HDIM + j;
#pragma unroll 8
    for (int i = 0; i < ICHUNK; i++) {
        float wv = wp[(size_t)i * HDIM];
        float4 ha = *(const float4*)&hs[i][bg * 8];
        float4 hb = *(const float4*)&hs[i][bg * 8 + 4];
        acc0 = fmaf(wv, ha.x, acc0);
        acc1 = fmaf(wv, ha.y, acc1);
        acc2 = fmaf(wv, ha.z, acc2);
        acc3 = fmaf(wv, ha.w, acc3);
        acc4 = fmaf(wv, hb.x, acc4);
        acc5 = fmaf(wv, hb.y, acc5);
        acc6 = fmaf(wv, hb.z, acc6);
        acc7 = fmaf(wv, hb.w, acc7);
    }
    float* po = g_opart + (size_t)ic * BATCH * HDIM + (size_t)(bg * 8) * HDIM + j;
    po[0*HDIM]=acc0; po[1*HDIM]=acc1; po[2*HDIM]=acc2; po[3*HDIM]=acc3;
    po[4*HDIM]=acc4; po[5*HDIM]=acc5; po[6*HDIM]=acc6; po[7*HDIM]=acc7;
}

// fold 32 partials + bias into output. grid 128 x 256 threads
__global__ void oreduce_kernel(const float* __restrict__ bias,
                               float* __restrict__ out) {
    const int idx = blockIdx.x * 256 + threadIdx.x;   // 0..32767
    float s = bias[idx & (HDIM - 1)];
#pragma unroll
    for (int p = 0; p < QSPLIT; p++)
        s += g_opart[p * BATCH * HDIM + idx];
    out[idx] = s;
}

extern "C" void kernel_launch(void* const* d_in, const int* in_sizes, int n_in,
                              void* d_out, int out_size) {
    const float* hidden = (const float*)d_in[0];
    const float* kv     = (const float*)d_in[1];
    const int*   btab   = (const int*)d_in[2];
    const int*   slen   = (const int*)d_in[3];
    const float* w_attn = (const float*)d_in[4];
    const float* b_attn = (const float*)d_in[5];
    const float* w_proj = (const float*)d_in[6];
    const float* b_proj = (const float*)d_in[7];
    float* out = (float*)d_out;

    qproj_kernel<<<dim3(16, QSPLIT), 256>>>(hidden, w_attn);
    attn_kernel<<<dim3(NHEADS, BATCH, KVSPLIT), 256>>>(kv, btab, slen, b_attn);
    oproj_kernel<<<dim3(16, QSPLIT), 256>>>(w_proj);
    oreduce_kernel<<<BATCH * HDIM / 256, 256>>>(b_proj, out);
}

// round 13
// speedup vs baseline: 1.3263x; 1.3263x over previous
#include <cuda_runtime.h>
#include <math_constants.h>

#define BATCH 32
#define HDIM 1024
#define NHEADS 16
#define HD 64
#define BS 16
#define MAX_KV 2048
#define BLOCKS_PER_SEQ 128
#define SCALE 0.125f

#define QSPLIT 32         // i-chunks for projections (1024/32)
#define ICHUNK 32
#define KVSPLIT 8         // splits over KV sequence
#define CHUNK 256         // tokens per split

// scratch (allocation-free rule: device globals)
__device__ float  g_qpart[QSPLIT * BATCH * HDIM];          // 4 MB
__device__ float  g_opart[QSPLIT * BATCH * HDIM];          // 4 MB
__device__ float  g_q    [BATCH * HDIM];
__device__ float  g_part [KVSPLIT * BATCH * NHEADS * HD];  // 1 MB
__device__ float  g_l    [KVSPLIT * BATCH * NHEADS];       // denom per split
__device__ float  g_attn [BATCH * HDIM];

#if defined(__CUDA_ARCH__) && (__CUDA_ARCH__ >= 900)
#define GRID_DEP_SYNC() cudaGridDependencySynchronize()
#else
#define GRID_DEP_SYNC()
#endif

// ---------------------------------------------------------------------------
// qproj partial: g_qpart[ic][b][j] = sum_{i in chunk} h[b][i]*w[i][j]
// grid (16 j-tiles, QSPLIT i-chunks) = 512 CTAs, 256 thr = 64 j x 4 bgroups(x8)
// First kernel: no PDL sync needed.
// ---------------------------------------------------------------------------
__global__ void qproj_kernel(const float* __restrict__ h,
                             const float* __restrict__ w) {
    const int jt = blockIdx.x;          // 0..15
    const int ic = blockIdx.y;          // 0..QSPLIT-1
    const int tid = threadIdx.x;
    const int j  = jt * 64 + (tid & 63);
    const int bg = tid >> 6;            // 0..3 -> batches bg*8..bg*8+7

    __shared__ float hs[ICHUNK][BATCH]; // [i][b], 4 KB
    for (int idx = tid; idx < ICHUNK * BATCH; idx += 256) {
        int i = idx >> 5, b = idx & 31;
        hs[i][b] = h[b * HDIM + ic * ICHUNK + i];
    }
    __syncthreads();

    float acc0=0,acc1=0,acc2=0,acc3=0,acc4=0,acc5=0,acc6=0,acc7=0;
    const float* wp = w + (size_t)(ic * ICHUNK) * (3 * HDIM) + j;
#pragma unroll 8
    for (int i = 0; i < ICHUNK; i++) {
        float wv = wp[(size_t)i * (3 * HDIM)];
        float4 ha = *(const float4*)&hs[i][bg * 8];
        float4 hb = *(const float4*)&hs[i][bg * 8 + 4];
        acc0 = fmaf(wv, ha.x, acc0);
        acc1 = fmaf(wv, ha.y, acc1);
        acc2 = fmaf(wv, ha.z, acc2);
        acc3 = fmaf(wv, ha.w, acc3);
        acc4 = fmaf(wv, hb.x, acc4);
        acc5 = fmaf(wv, hb.y, acc5);
        acc6 = fmaf(wv, hb.z, acc6);
        acc7 = fmaf(wv, hb.w, acc7);
    }
    float* po = g_qpart + (size_t)ic * BATCH * HDIM + (size_t)(bg * 8) * HDIM + j;
    po[0*HDIM]=acc0; po[1*HDIM]=acc1; po[2*HDIM]=acc2; po[3*HDIM]=acc3;
    po[4*HDIM]=acc4; po[5*HDIM]=acc5; po[6*HDIM]=acc6; po[7*HDIM]=acc7;
}

// fold 32 partials + bias. grid 128 x 256 threads. PDL: sync before g_qpart.
__global__ void qreduce_kernel(const float* __restrict__ bias) {
    const int idx = blockIdx.x * 256 + threadIdx.x;   // 0..32767
    float s = bias[idx & (HDIM - 1)];                 // input: safe pre-sync
    GRID_DEP_SYNC();
#pragma unroll
    for (int p = 0; p < QSPLIT; p++)
        s += g_qpart[p * BATCH * HDIM + idx];
    g_q[idx] = s;
}

// ---------------------------------------------------------------------------
// Flash-decode attention, split-KV. grid (NHEADS, BATCH, KVSPLIT), 256 thr.
// PDL: block-table load + empty-split handling run pre-sync; sync before g_q.
// ---------------------------------------------------------------------------
__global__ void attn_kernel(const float* __restrict__ kv,
                            const int* __restrict__ btab,
                            const int* __restrict__ slen) {
    const int n  = blockIdx.x;
    const int b  = blockIdx.y;
    const int sp = blockIdx.z;
    const int tid = threadIdx.x;
    const int L = slen[b];                 // input: safe pre-sync
    const int start = sp * CHUNK;
    const int end = min(L, start + CHUNK);
    const int pidx = (sp * BATCH + b) * NHEADS + n;

    if (start >= end) {   // empty split: neutral partial (uniform across CTA)
        if (tid < HD) g_part[pidx * HD + tid] = 0.f;
        if (tid == 0) g_l[pidx] = 0.f;
        return;
    }

    __shared__ float sq[HD];
    __shared__ int   sbt[CHUNK / BS];          // 16 block ids for this chunk
    __shared__ float smacc[16][HD];            // per half-warp V accum
    __shared__ float sml[16];                  // per half-warp denom

    if (tid < CHUNK / BS)
        sbt[tid] = btab[b * BLOCKS_PER_SEQ + (start >> 4) + tid];  // input

    GRID_DEP_SYNC();                            // wait for qreduce's g_q

    if (tid < HD) sq[tid] = g_q[b * HDIM + n * HD + tid] * SCALE;
    __syncthreads();

    const int lane = tid & 31;
    const int warp = tid >> 5;        // 0..7
    const int half = lane >> 4;       // 0/1
    const int hl   = lane & 15;       // lane within half-warp
    const int hw   = warp * 2 + half; // half-warp id 0..15
    const float4 q4 = ((const float4*)sq)[hl];

    const float* kbase = kv;
    const float* vbase = kv + (size_t)4096 * BS * NHEADS * HD;

    float l = 0.f;
    float4 acc = make_float4(0.f, 0.f, 0.f, 0.f);

    // uniform iteration count across the whole CTA
    const int NIT = (end - start + 15) >> 4;
#pragma unroll 4
    for (int it = 0; it < NIT; it++) {
        const int t = start + hw + it * 16;
        const bool valid = (t < end);
        // redirect invalid lanes to a safe address within the chunk
        const int ts = valid ? t : start;
        const int blk = sbt[(ts - start) >> 4];
        const size_t off = (((size_t)blk * BS + (ts & 15)) * NHEADS + n) * HD + hl * 4;
        const float4 k4 = __ldcs((const float4*)(kbase + off));
        const float4 v4 = __ldcs((const float4*)(vbase + off));
        float p = fmaf(k4.x, q4.x, fmaf(k4.y, q4.y, fmaf(k4.z, q4.z, k4.w * q4.w)));
#pragma unroll
        for (int o = 8; o > 0; o >>= 1)
            p += __shfl_xor_sync(0xffffffffu, p, o);
        if (!valid) p = -CUDART_INF_F;          // exp(-inf) = 0: neutral
        const float e = __expf(fminf(p, 60.f));
        acc.x = fmaf(e, v4.x, acc.x);
        acc.y = fmaf(e, v4.y, acc.y);
        acc.z = fmaf(e, v4.z, acc.z);
        acc.w = fmaf(e, v4.w, acc.w);
        l += e;
    }

    ((float4*)smacc[hw])[hl] = acc;
    if (hl == 0) sml[hw] = l;
    __syncthreads();

    if (tid < HD) {
        float num = 0.f, den = 0.f;
#pragma unroll
        for (int i = 0; i < 16; i++) {
            num += smacc[i][tid];
            den += sml[i];
        }
        g_part[pidx * HD + tid] = num;
        if (tid == 0) g_l[pidx] = den;
    }
}

// Merge KVSPLIT partials (plain sums). 8192 threads: (b,n,d4) per thread.
// PDL: sync before reading g_part/g_l.
__global__ void attn_reduce_kernel() {
    const int gid = blockIdx.x * 256 + threadIdx.x;  // 0..8191
    const int bn = gid >> 4;              // 0..511 = b*NHEADS+n
    const int d4 = gid & 15;              // float4 index within HD
    const int b = bn >> 4, n = bn & 15;

    GRID_DEP_SYNC();

    float4 num = make_float4(0.f, 0.f, 0.f, 0.f);
    float den = 0.f;
#pragma unroll
    for (int s = 0; s < KVSPLIT; s++) {
        const int pidx = (s * BATCH + b) * NHEADS + n;
        const float4 p = ((const float4*)(g_part + pidx * HD))[d4];
        num.x += p.x; num.y += p.y; num.z += p.z; num.w += p.w;
        den += g_l[pidx];
    }
    const float inv = 1.0f / den;
    float4 o = make_float4(num.x * inv, num.y * inv, num.z * inv, num.w * inv);
    ((float4*)(g_attn + b * HDIM + n * HD))[d4] = o;
}

// ---------------------------------------------------------------------------
// oproj partial. PDL: preload the 8 KB weight tile into smem BEFORE the sync
// (independent of attn) -> weight streaming overlaps attn/attn_reduce tail,
// and removes the 4x redundant per-bgroup weight reads.
// ---------------------------------------------------------------------------
__global__ void oproj_kernel(const float* __restrict__ w) {
    const int jt = blockIdx.x;          // 0..15
    const int ic = blockIdx.y;          // 0..QSPLIT-1
    const int tid = threadIdx.x;
    const int j  = tid & 63;            // local j within tile
    const int bg = tid >> 6;            // 0..3 -> batches bg*8..bg*8+7

    __shared__ float hs[ICHUNK][BATCH]; // [i][b], 4 KB
    __shared__ float ws[ICHUNK][64];    // weight tile, 8 KB

    // ---- pre-sync: stage weights (independent of predecessors) ----
    for (int idx = tid; idx < ICHUNK * 64; idx += 256) {
        const int i = idx >> 6, jj = idx & 63;
        ws[i][jj] = w[(size_t)(ic * ICHUNK + i) * HDIM + jt * 64 + jj];
    }

    GRID_DEP_SYNC();                    // wait for attn_reduce's g_attn

    for (int idx = tid; idx < ICHUNK * BATCH; idx += 256) {
        int i = idx >> 5, b = idx & 31;
        hs[i][b] = g_attn[b * HDIM + ic * ICHUNK + i];
    }
    __syncthreads();

    float acc0=0,acc1=0,acc2=0,acc3=0,acc4=0,acc5=0,acc6=0,acc7=0;
#pragma unroll 8
    for (int i = 0; i < ICHUNK; i++) {
        float wv = ws[i][j];
        float4 ha = *(const float4*)&hs[i][bg * 8];
        float4 hb = *(const float4*)&hs[i][bg * 8 + 4];
        acc0 = fmaf(wv, ha.x, acc0);
        acc1 = fmaf(wv, ha.y, acc1);
        acc2 = fmaf(wv, ha.z, acc2);
        acc3 = fmaf(wv, ha.w, acc3);
        acc4 = fmaf(wv, hb.x, acc4);
        acc5 = fmaf(wv, hb.y, acc5);
        acc6 = fmaf(wv, hb.z, acc6);
        acc7 = fmaf(wv, hb.w, acc7);
    }
    float* po = g_opart + (size_t)ic * BATCH * HDIM + (size_t)(bg * 8) * HDIM
              + jt * 64 + j;
    po[0*HDIM]=acc0; po[1*HDIM]=acc1; po[2*HDIM]=acc2; po[3*HDIM]=acc3;
    po[4*HDIM]=acc4; po[5*HDIM]=acc5; po[6*HDIM]=acc6; po[7*HDIM]=acc7;
}

// fold 32 partials + bias into output. PDL: sync before g_opart.
__global__ void oreduce_kernel(const float* __restrict__ bias,
                               float* __restrict__ out) {
    const int idx = blockIdx.x * 256 + threadIdx.x;   // 0..32767
    float s = bias[idx & (HDIM - 1)];                 // input: safe pre-sync
    GRID_DEP_SYNC();
#pragma unroll
    for (int p = 0; p < QSPLIT; p++)
        s += g_opart[p * BATCH * HDIM + idx];
    out[idx] = s;
}

// ---------------------------------------------------------------------------
// Host: launch with programmatic stream serialization on dependent kernels.
// ---------------------------------------------------------------------------
template <typename F, typename... Args>
static void launch_pdl(F f, dim3 grid, dim3 block, Args... args) {
    cudaLaunchConfig_t cfg = {};
    cfg.gridDim = grid;
    cfg.blockDim = block;
    cfg.dynamicSmemBytes = 0;
    cfg.stream = 0;
    cudaLaunchAttribute attr[1];
    attr[0].id = cudaLaunchAttributeProgrammaticStreamSerialization;
    attr[0].val.programmaticStreamSerializationAllowed = 1;
    cfg.attrs = attr;
    cfg.numAttrs = 1;
    cudaLaunchKernelEx(&cfg, f, args...);
}

extern "C" void kernel_launch(void* const* d_in, const int* in_sizes, int n_in,
                              void* d_out, int out_size) {
    const float* hidden = (const float*)d_in[0];
    const float* kv     = (const float*)d_in[1];
    const int*   btab   = (const int*)d_in[2];
    const int*   slen   = (const int*)d_in[3];
    const float* w_attn = (const float*)d_in[4];
    const float* b_attn = (const float*)d_in[5];
    const float* w_proj = (const float*)d_in[6];
    const float* b_proj = (const float*)d_in[7];
    float* out = (float*)d_out;

    qproj_kernel<<<dim3(16, QSPLIT), 256>>>(hidden, w_attn);
    launch_pdl(qreduce_kernel, dim3(BATCH * HDIM / 256), dim3(256), b_attn);
    launch_pdl(attn_kernel, dim3(NHEADS, BATCH, KVSPLIT), dim3(256),
               kv, btab, slen);
    launch_pdl(attn_reduce_kernel,
               dim3(BATCH * NHEADS * (HD / 4) / 256), dim3(256));
    launch_pdl(oproj_kernel, dim3(16, QSPLIT), dim3(256), w_proj);
    launch_pdl(oreduce_kernel, dim3(BATCH * HDIM / 256), dim3(256),
               b_proj, out);
}

// round 15
// speedup vs baseline: 1.3823x; 1.0423x over previous
#include <cuda_runtime.h>
#include <math_constants.h>

#define BATCH 32
#define HDIM 1024
#define NHEADS 16
#define HD 64
#define BS 16
#define MAX_KV 2048
#define BLOCKS_PER_SEQ 128
#define SCALE 0.125f

#define QSPLIT 32         // i-chunks for projections (1024/32)
#define ICHUNK 32
#define KVSPLIT 8         // splits over KV sequence
#define CHUNK 256         // tokens per split

// scratch (allocation-free rule: device globals)
__device__ float  g_qpart[QSPLIT * BATCH * HDIM];          // 4 MB
__device__ float  g_opart[QSPLIT * BATCH * HDIM];          // 4 MB
__device__ float  g_q    [BATCH * HDIM];
__device__ float  g_part [KVSPLIT * BATCH * NHEADS * HD];  // 1 MB
__device__ float  g_l    [KVSPLIT * BATCH * NHEADS];       // denom per split
__device__ float  g_attn [BATCH * HDIM];

#if defined(__CUDA_ARCH__) && (__CUDA_ARCH__ >= 900)
#define GRID_DEP_SYNC() cudaGridDependencySynchronize()
#else
#define GRID_DEP_SYNC()
#endif

// ---------------------------------------------------------------------------
// qproj partial: g_qpart[ic][b][j] = sum_{i in chunk} h[b][i]*w[i][j]
// grid (16 j-tiles, QSPLIT i-chunks) = 512 CTAs, 256 thr = 64 j x 4 bgroups(x8)
// ---------------------------------------------------------------------------
__global__ void qproj_kernel(const float* __restrict__ h,
                             const float* __restrict__ w) {
    const int jt = blockIdx.x;          // 0..15
    const int ic = blockIdx.y;          // 0..QSPLIT-1
    const int tid = threadIdx.x;
    const int j  = jt * 64 + (tid & 63);
    const int bg = tid >> 6;            // 0..3 -> batches bg*8..bg*8+7

    __shared__ float hs[ICHUNK][BATCH]; // [i][b], 4 KB
    for (int idx = tid; idx < ICHUNK * BATCH; idx += 256) {
        int i = idx >> 5, b = idx & 31;
        hs[i][b] = h[b * HDIM + ic * ICHUNK + i];
    }
    __syncthreads();

    float acc0=0,acc1=0,acc2=0,acc3=0,acc4=0,acc5=0,acc6=0,acc7=0;
    const float* wp = w + (size_t)(ic * ICHUNK) * (3 * HDIM) + j;
#pragma unroll 8
    for (int i = 0; i < ICHUNK; i++) {
        float wv = wp[(size_t)i * (3 * HDIM)];
        float4 ha = *(const float4*)&hs[i][bg * 8];
        float4 hb = *(const float4*)&hs[i][bg * 8 + 4];
        acc0 = fmaf(wv, ha.x, acc0);
        acc1 = fmaf(wv, ha.y, acc1);
        acc2 = fmaf(wv, ha.z, acc2);
        acc3 = fmaf(wv, ha.w, acc3);
        acc4 = fmaf(wv, hb.x, acc4);
        acc5 = fmaf(wv, hb.y, acc5);
        acc6 = fmaf(wv, hb.z, acc6);
        acc7 = fmaf(wv, hb.w, acc7);
    }
    float* po = g_qpart + (size_t)ic * BATCH * HDIM + (size_t)(bg * 8) * HDIM + j;
    po[0*HDIM]=acc0; po[1*HDIM]=acc1; po[2*HDIM]=acc2; po[3*HDIM]=acc3;
    po[4*HDIM]=acc4; po[5*HDIM]=acc5; po[6*HDIM]=acc6; po[7*HDIM]=acc7;
}

// fold 32 partials + bias, float4 per thread. 8192 threads in 32 CTAs.
__global__ void qreduce_kernel(const float* __restrict__ bias) {
    const int idx4 = blockIdx.x * 256 + threadIdx.x;   // 0..8191 (float4 idx)
    const int jb = (idx4 * 4) & (HDIM - 1);
    float4 s = *(const float4*)(bias + jb);            // input: pre-sync
    GRID_DEP_SYNC();
#pragma unroll
    for (int p = 0; p < QSPLIT; p++) {
        const float4 v = ((const float4*)g_qpart)[p * BATCH * HDIM / 4 + idx4];
        s.x += v.x; s.y += v.y; s.z += v.z; s.w += v.w;
    }
    ((float4*)g_q)[idx4] = s;
}

// ---------------------------------------------------------------------------
// Flash-decode attention, split-KV. grid (NHEADS, BATCH, KVSPLIT), 256 thr.
// Empty splits exit without writing (attn_reduce predicates on slen).
// ---------------------------------------------------------------------------
__global__ void __launch_bounds__(256) attn_kernel(
                            const float* __restrict__ kv,
                            const int* __restrict__ btab,
                            const int* __restrict__ slen) {
    const int n  = blockIdx.x;
    const int b  = blockIdx.y;
    const int sp = blockIdx.z;
    const int tid = threadIdx.x;
    const int L = slen[b];                 // input: safe pre-sync
    const int start = sp * CHUNK;
    const int end = min(L, start + CHUNK);
    const int pidx = (sp * BATCH + b) * NHEADS + n;

    if (start >= end) return;              // empty split: nothing to produce

    __shared__ float sq[HD];
    __shared__ int   sbt[CHUNK / BS];          // 16 block ids for this chunk
    __shared__ float smacc[16][HD];            // per half-warp V accum
    __shared__ float sml[16];                  // per half-warp denom

    if (tid < CHUNK / BS)
        sbt[tid] = btab[b * BLOCKS_PER_SEQ + (start >> 4) + tid];  // input

    GRID_DEP_SYNC();                            // wait for qreduce's g_q

    if (tid < HD) sq[tid] = g_q[b * HDIM + n * HD + tid] * SCALE;
    __syncthreads();

    const int lane = tid & 31;
    const int warp = tid >> 5;        // 0..7
    const int half = lane >> 4;       // 0/1
    const int hl   = lane & 15;       // lane within half-warp
    const int hw   = warp * 2 + half; // half-warp id 0..15
    const float4 q4 = ((const float4*)sq)[hl];

    const float* kbase = kv;
    const float* vbase = kv + (size_t)4096 * BS * NHEADS * HD;

    float l = 0.f;
    float4 acc = make_float4(0.f, 0.f, 0.f, 0.f);

    // uniform iteration count across the whole CTA
    const int NIT = (end - start + 15) >> 4;
#pragma unroll 8
    for (int it = 0; it < NIT; it++) {
        const int t = start + hw + it * 16;
        const bool valid = (t < end);
        // redirect invalid lanes to a safe address within the chunk
        const int ts = valid ? t : start;
        const int blk = sbt[(ts - start) >> 4];
        const size_t off = (((size_t)blk * BS + (ts & 15)) * NHEADS + n) * HD + hl * 4;
        const float4 k4 = __ldcs((const float4*)(kbase + off));
        const float4 v4 = __ldcs((const float4*)(vbase + off));
        float p = fmaf(k4.x, q4.x, fmaf(k4.y, q4.y, fmaf(k4.z, q4.z, k4.w * q4.w)));
#pragma unroll
        for (int o = 8; o > 0; o >>= 1)
            p += __shfl_xor_sync(0xffffffffu, p, o);
        if (!valid) p = -CUDART_INF_F;          // exp(-inf) = 0: neutral
        const float e = __expf(fminf(p, 60.f));
        acc.x = fmaf(e, v4.x, acc.x);
        acc.y = fmaf(e, v4.y, acc.y);
        acc.z = fmaf(e, v4.z, acc.z);
        acc.w = fmaf(e, v4.w, acc.w);
        l += e;
    }

    ((float4*)smacc[hw])[hl] = acc;
    if (hl == 0) sml[hw] = l;
    __syncthreads();

    if (tid < HD) {
        float num = 0.f, den = 0.f;
#pragma unroll
        for (int i = 0; i < 16; i++) {
            num += smacc[i][tid];
            den += sml[i];
        }
        g_part[pidx * HD + tid] = num;
        if (tid == 0) g_l[pidx] = den;
    }
}

// Merge valid KVSPLIT partials (plain sums). 8192 threads: (b,n,d4)/thread.
// Splits with s*CHUNK >= L were never written -> predicated off here.
__global__ void attn_reduce_kernel(const int* __restrict__ slen) {
    const int gid = blockIdx.x * 256 + threadIdx.x;  // 0..8191
    const int bn = gid >> 4;              // 0..511 = b*NHEADS+n
    const int d4 = gid & 15;              // float4 index within HD
    const int b = bn >> 4, n = bn & 15;
    const int L = slen[b];                // input: safe pre-sync

    GRID_DEP_SYNC();

    float4 num = make_float4(0.f, 0.f, 0.f, 0.f);
    float den = 0.f;
#pragma unroll
    for (int s = 0; s < KVSPLIT; s++) {
        if (s * CHUNK < L) {
            const int pidx = (s * BATCH + b) * NHEADS + n;
            const float4 p = ((const float4*)(g_part + pidx * HD))[d4];
            num.x += p.x; num.y += p.y; num.z += p.z; num.w += p.w;
            den += g_l[pidx];
        }
    }
    const float inv = 1.0f / den;
    float4 o = make_float4(num.x * inv, num.y * inv, num.z * inv, num.w * inv);
    ((float4*)(g_attn + b * HDIM + n * HD))[d4] = o;
}

// ---------------------------------------------------------------------------
// oproj partial: weights staged to smem pre-sync (overlaps attn tail).
// ---------------------------------------------------------------------------
__global__ void oproj_kernel(const float* __restrict__ w) {
    const int jt = blockIdx.x;          // 0..15
    const int ic = blockIdx.y;          // 0..QSPLIT-1
    const int tid = threadIdx.x;
    const int j  = tid & 63;            // local j within tile
    const int bg = tid >> 6;            // 0..3 -> batches bg*8..bg*8+7

    __shared__ float hs[ICHUNK][BATCH]; // [i][b], 4 KB
    __shared__ float ws[ICHUNK][64];    // weight tile, 8 KB

    // ---- pre-sync: stage weights (independent of predecessors) ----
    for (int idx = tid; idx < ICHUNK * 64; idx += 256) {
        const int i = idx >> 6, jj = idx & 63;
        ws[i][jj] = w[(size_t)(ic * ICHUNK + i) * HDIM + jt * 64 + jj];
    }

    GRID_DEP_SYNC();                    // wait for attn_reduce's g_attn

    for (int idx = tid; idx < ICHUNK * BATCH; idx += 256) {
        int i = idx >> 5, b = idx & 31;
        hs[i][b] = g_attn[b * HDIM + ic * ICHUNK + i];
    }
    __syncthreads();

    float acc0=0,acc1=0,acc2=0,acc3=0,acc4=0,acc5=0,acc6=0,acc7=0;
#pragma unroll 8
    for (int i = 0; i < ICHUNK; i++) {
        float wv = ws[i][j];
        float4 ha = *(const float4*)&hs[i][bg * 8];
        float4 hb = *(const float4*)&hs[i][bg * 8 + 4];
        acc0 = fmaf(wv, ha.x, acc0);
        acc1 = fmaf(wv, ha.y, acc1);
        acc2 = fmaf(wv, ha.z, acc2);
        acc3 = fmaf(wv, ha.w, acc3);
        acc4 = fmaf(wv, hb.x, acc4);
        acc5 = fmaf(wv, hb.y, acc5);
        acc6 = fmaf(wv, hb.z, acc6);
        acc7 = fmaf(wv, hb.w, acc7);
    }
    float* po = g_opart + (size_t)ic * BATCH * HDIM + (size_t)(bg * 8) * HDIM
              + jt * 64 + j;
    po[0*HDIM]=acc0; po[1*HDIM]=acc1; po[2*HDIM]=acc2; po[3*HDIM]=acc3;
    po[4*HDIM]=acc4; po[5*HDIM]=acc5; po[6*HDIM]=acc6; po[7*HDIM]=acc7;
}

// fold 32 partials + bias into output, float4 per thread. 32 CTAs.
__global__ void oreduce_kernel(const float* __restrict__ bias,
                               float* __restrict__ out) {
    const int idx4 = blockIdx.x * 256 + threadIdx.x;   // 0..8191
    const int jb = (idx4 * 4) & (HDIM - 1);
    float4 s = *(const float4*)(bias + jb);            // input: pre-sync
    GRID_DEP_SYNC();
#pragma unroll
    for (int p = 0; p < QSPLIT; p++) {
        const float4 v = ((const float4*)g_opart)[p * BATCH * HDIM / 4 + idx4];
        s.x += v.x; s.y += v.y; s.z += v.z; s.w += v.w;
    }
    ((float4*)out)[idx4] = s;
}

// ---------------------------------------------------------------------------
// Host: launch with programmatic stream serialization on dependent kernels.
// ---------------------------------------------------------------------------
template <typename F, typename... Args>
static void launch_pdl(F f, dim3 grid, dim3 block, Args... args) {
    cudaLaunchConfig_t cfg = {};
    cfg.gridDim = grid;
    cfg.blockDim = block;
    cfg.dynamicSmemBytes = 0;
    cfg.stream = 0;
    cudaLaunchAttribute attr[1];
    attr[0].id = cudaLaunchAttributeProgrammaticStreamSerialization;
    attr[0].val.programmaticStreamSerializationAllowed = 1;
    cfg.attrs = attr;
    cfg.numAttrs = 1;
    cudaLaunchKernelEx(&cfg, f, args...);
}

extern "C" void kernel_launch(void* const* d_in, const int* in_sizes, int n_in,
                              void* d_out, int out_size) {
    const float* hidden = (const float*)d_in[0];
    const float* kv     = (const float*)d_in[1];
    const int*   btab   = (const int*)d_in[2];
    const int*   slen   = (const int*)d_in[3];
    const float* w_attn = (const float*)d_in[4];
    const float* b_attn = (const float*)d_in[5];
    const float* w_proj = (const float*)d_in[6];
    const float* b_proj = (const float*)d_in[7];
    float* out = (float*)d_out;

    qproj_kernel<<<dim3(16, QSPLIT), 256>>>(hidden, w_attn);
    launch_pdl(qreduce_kernel, dim3(BATCH * HDIM / 1024), dim3(256), b_attn);
    launch_pdl(attn_kernel, dim3(NHEADS, BATCH, KVSPLIT), dim3(256),
               kv, btab, slen);
    launch_pdl(attn_reduce_kernel,
               dim3(BATCH * NHEADS * (HD / 4) / 256), dim3(256), slen);
    launch_pdl(oproj_kernel, dim3(16, QSPLIT), dim3(256), w_proj);
    launch_pdl(oreduce_kernel, dim3(BATCH * HDIM / 1024), dim3(256),
               b_proj, out);
}